// round 4
// baseline (speedup 1.0000x reference)
#include <cuda_runtime.h>

typedef unsigned long long u64;

// ---- packed f32x2 helpers (sm_103a) ----
__device__ __forceinline__ u64 pack2(float lo, float hi) {
    u64 d;
    asm("mov.b64 %0, {%1, %2};" : "=l"(d) : "r"(__float_as_uint(lo)), "r"(__float_as_uint(hi)));
    return d;
}
__device__ __forceinline__ void unpack2(u64 v, float& lo, float& hi) {
    unsigned a, b;
    asm("mov.b64 {%0, %1}, %2;" : "=r"(a), "=r"(b) : "l"(v));
    lo = __uint_as_float(a); hi = __uint_as_float(b);
}
__device__ __forceinline__ u64 fma2(u64 a, u64 b, u64 c) {
    u64 d;
    asm("fma.rn.f32x2 %0, %1, %2, %3;" : "=l"(d) : "l"(a), "l"(b), "l"(c));
    return d;
}
__device__ __forceinline__ u64 mul2(u64 a, u64 b) {
    u64 d;
    asm("mul.rn.f32x2 %0, %1, %2;" : "=l"(d) : "l"(a), "l"(b));
    return d;
}
__device__ __forceinline__ u64 add2(u64 a, u64 b) {
    u64 d;
    asm("add.rn.f32x2 %0, %1, %2;" : "=l"(d) : "l"(a), "l"(b));
    return d;
}
__device__ __forceinline__ u64 relu2(u64 v) {
    float lo, hi; unpack2(v, lo, hi);          // reg-pair alias, free in SASS
    lo = fmaxf(lo, 0.0f); hi = fmaxf(hi, 0.0f);
    return pack2(lo, hi);
}

// ---- problem constants ----
constexpr int W_DIM = 4096;
constexpr int C_DIM = 64;
constexpr int L_SEG = 512;            // outputs per warp
constexpr int SEGS  = W_DIM / L_SEG;  // 8
constexpr int BH    = 16 * 21;        // 336 rows
constexpr int PF    = 8;              // x prefetch distance (steps)
constexpr int WU    = 64;             // warmup steps (>= 52 needed)
constexpr int T_TOT = WU + L_SEG;     // 576 steps total

// Cross-correlation, zero pad. pad_lo: d=1 -> 3, d=2 -> 7, d=4 -> 14.
// y1[w] = relu(sum_k x [w- 3+  k] * w1[k])
// y2[w] = relu(sum_k y1[w- 7+ 2k] * w2[k])   (y1 := 0 outside [0,W))
// y3[w] = relu(sum_k y2[w-14+ 4k] * w3[k])   (y2 := 0 outside [0,W))
//
// Software-pipelined schedule (per warp, lane = 2 packed channels, t0 = s0-36):
//   step i: LOAD  x pos t0+i+PF       -> xr[(i+PF)&15]
//           STAGE1 y1 @ t0+i-4        -> y1r[i&15]   (x steps i-7..i)
//           STAGE2 y2 @ t0+i-12       -> y2r[i&31]   (y1 steps i-15..i-1, odd lags)
//           STAGE3 y3 @ t0+i-28       -> store       (y2 steps i-30..i-2, lag%4==2)
// Three independent fma chains per step. All ring indices static (unroll 32).
// Addressing: running pointers bumped 32*C_DIM per block; in-body offsets are
// compile-time immediates (u*256B) -> no per-step address arithmetic.

#define LOAD_STEP(u)                                                           \
    {                                                                          \
        u64 xv;                                                                \
        if (BOUNDARY) {                                                        \
            const int t = tld + (u);                                           \
            xv = (t >= 0 && t < W_DIM) ? *(const u64*)(lp + (u) * C_DIM) : 0ull; \
        } else {                                                               \
            xv = *(const u64*)(lp + (u) * C_DIM);                              \
        }                                                                      \
        xr[((u) + PF) & 15] = xv;                                              \
    }

#define STAGE1(u)                                                              \
    {                                                                          \
        u64 a0 = mul2(xr[((u) - 7) & 15], w1r[0]);                             \
        u64 a1 = mul2(xr[((u) - 6) & 15], w1r[1]);                             \
        a0 = fma2(xr[((u) - 5) & 15], w1r[2], a0);                             \
        a1 = fma2(xr[((u) - 4) & 15], w1r[3], a1);                             \
        a0 = fma2(xr[((u) - 3) & 15], w1r[4], a0);                             \
        a1 = fma2(xr[((u) - 2) & 15], w1r[5], a1);                             \
        a0 = fma2(xr[((u) - 1) & 15], w1r[6], a0);                             \
        a1 = fma2(xr[((u) - 0) & 15], w1r[7], a1);                             \
        u64 y1v = relu2(add2(a0, a1));                                         \
        if (BOUNDARY) {                                                        \
            const int p1 = tld + (u) - PF - 4;                                 \
            if (p1 < 0 || p1 >= W_DIM) y1v = 0ull;                             \
        }                                                                      \
        y1r[(u) & 15] = y1v;                                                   \
    }

#define STAGE2(u)                                                              \
    {                                                                          \
        u64 b0 = mul2(y1r[((u) - 15) & 15], w2r[0]);                           \
        u64 b1 = mul2(y1r[((u) - 13) & 15], w2r[1]);                           \
        b0 = fma2(y1r[((u) - 11) & 15], w2r[2], b0);                           \
        b1 = fma2(y1r[((u) -  9) & 15], w2r[3], b1);                           \
        b0 = fma2(y1r[((u) -  7) & 15], w2r[4], b0);                           \
        b1 = fma2(y1r[((u) -  5) & 15], w2r[5], b1);                           \
        b0 = fma2(y1r[((u) -  3) & 15], w2r[6], b0);                           \
        b1 = fma2(y1r[((u) -  1) & 15], w2r[7], b1);                           \
        u64 y2v = relu2(add2(b0, b1));                                         \
        if (BOUNDARY) {                                                        \
            const int p2 = tld + (u) - PF - 12;                                \
            if (p2 < 0 || p2 >= W_DIM) y2v = 0ull;                             \
        }                                                                      \
        y2r[(u) & 31] = y2v;                                                   \
    }

#define STAGE3_STORE(u)                                                        \
    {                                                                          \
        u64 c0 = mul2(y2r[((u) - 30) & 31], w3r[0]);                           \
        u64 c1 = mul2(y2r[((u) - 26) & 31], w3r[1]);                           \
        c0 = fma2(y2r[((u) - 22) & 31], w3r[2], c0);                           \
        c1 = fma2(y2r[((u) - 18) & 31], w3r[3], c1);                           \
        c0 = fma2(y2r[((u) - 14) & 31], w3r[4], c0);                           \
        c1 = fma2(y2r[((u) - 10) & 31], w3r[5], c1);                           \
        c0 = fma2(y2r[((u) -  6) & 31], w3r[6], c0);                           \
        c1 = fma2(y2r[((u) -  2) & 31], w3r[7], c1);                           \
        const u64 y3v = relu2(add2(c0, c1));                                   \
        __stcs((u64*)(sp + (u) * C_DIM), y3v);                                 \
    }

template<bool BOUNDARY>
__device__ __forceinline__ void run_seg(
    const float* __restrict__ x,
    const u64* w1r, const u64* w2r, const u64* w3r,
    float* __restrict__ out,
    int bh, int seg, int lane)
{
    const int s0 = seg * L_SEG;
    const int t0 = s0 - 36;

    // running load pointer: points at position (t0 + ib + PF), lane offset applied
    const float* lp = x + ((long long)bh * W_DIM + (t0 + PF)) * C_DIM + 2 * lane;
    // running store pointer: main loop starts at i = WU -> position s0
    float* sp = out + ((long long)bh * W_DIM + s0) * C_DIM + 2 * lane;
    // boundary predicate base: t = tld + u is the loaded position at offset u
    int tld = t0 + PF;

    u64 xr[16], y1r[16], y2r[32];
    #pragma unroll
    for (int j = 0; j < 16; ++j) xr[j]  = 0ull;
    #pragma unroll
    for (int j = 0; j < 16; ++j) y1r[j] = 0ull;
    #pragma unroll
    for (int j = 0; j < 32; ++j) y2r[j] = 0ull;

    // preload positions t0+0 .. t0+PF-1 into slots 0..PF-1
    #pragma unroll
    for (int j = 0; j < PF; ++j) {
        if (BOUNDARY) {
            const int t = t0 + j;
            xr[j] = (t >= 0 && t < W_DIM)
                  ? *(const u64*)(lp + (j - PF) * C_DIM) : 0ull;
        } else {
            xr[j] = *(const u64*)(lp + (j - PF) * C_DIM);
        }
    }

    // warmup: stages 1-2 only (fills y1/y2 rings)
    for (int ib = 0; ib < WU; ib += 32) {
        #pragma unroll
        for (int u = 0; u < 32; ++u) {
            LOAD_STEP(u)
            STAGE1(u)
            STAGE2(u)
        }
        lp  += 32 * C_DIM;
        tld += 32;
    }

    // main: all stages, unconditional store
    for (int ib = WU; ib < T_TOT; ib += 32) {
        #pragma unroll
        for (int u = 0; u < 32; ++u) {
            LOAD_STEP(u)
            STAGE1(u)
            STAGE2(u)
            STAGE3_STORE(u)
        }
        lp  += 32 * C_DIM;
        sp  += 32 * C_DIM;
        tld += 32;
    }
}

__global__ void __launch_bounds__(128)
conv_stack_kernel(const float* __restrict__ x,
                  const float* __restrict__ w1,
                  const float* __restrict__ w2,
                  const float* __restrict__ w3,
                  float* __restrict__ out)
{
    const int warp = blockIdx.x * 4 + (threadIdx.x >> 5);
    const int lane = threadIdx.x & 31;

    const int bh  = warp >> 3;        // warp / SEGS
    const int seg = warp & 7;         // warp % SEGS

    // per-channel-pair weights (8 taps each), contiguous float2 at k*64 + 2*lane
    u64 w1r[8], w2r[8], w3r[8];
    #pragma unroll
    for (int k = 0; k < 8; ++k) {
        w1r[k] = *(const u64*)(w1 + k * C_DIM + 2 * lane);
        w2r[k] = *(const u64*)(w2 + k * C_DIM + 2 * lane);
        w3r[k] = *(const u64*)(w3 + k * C_DIM + 2 * lane);
    }

    if (seg == 0 || seg == SEGS - 1) {
        run_seg<true >(x, w1r, w2r, w3r, out, bh, seg, lane);
    } else {
        run_seg<false>(x, w1r, w2r, w3r, out, bh, seg, lane);
    }
}

extern "C" void kernel_launch(void* const* d_in, const int* in_sizes, int n_in,
                              void* d_out, int out_size)
{
    const float* x  = (const float*)d_in[0];
    const float* w1 = (const float*)d_in[1];
    const float* w2 = (const float*)d_in[2];
    const float* w3 = (const float*)d_in[3];
    float* out = (float*)d_out;

    (void)in_sizes; (void)n_in; (void)out_size;

    // 336 rows * 8 segs = 2688 warps -> 672 blocks of 128 threads, one launch
    conv_stack_kernel<<<(BH * SEGS) / 4, 128>>>(x, w1, w2, w3, out);
}

// round 5
// speedup vs baseline: 1.1341x; 1.1341x over previous
#include <cuda_runtime.h>

typedef unsigned long long u64;

// ---- packed f32x2 helpers (sm_103a) ----
__device__ __forceinline__ u64 pack2(float lo, float hi) {
    u64 d;
    asm("mov.b64 %0, {%1, %2};" : "=l"(d) : "r"(__float_as_uint(lo)), "r"(__float_as_uint(hi)));
    return d;
}
__device__ __forceinline__ void unpack2(u64 v, float& lo, float& hi) {
    unsigned a, b;
    asm("mov.b64 {%0, %1}, %2;" : "=r"(a), "=r"(b) : "l"(v));
    lo = __uint_as_float(a); hi = __uint_as_float(b);
}
__device__ __forceinline__ u64 fma2(u64 a, u64 b, u64 c) {
    u64 d;
    asm("fma.rn.f32x2 %0, %1, %2, %3;" : "=l"(d) : "l"(a), "l"(b), "l"(c));
    return d;
}
__device__ __forceinline__ u64 mul2(u64 a, u64 b) {
    u64 d;
    asm("mul.rn.f32x2 %0, %1, %2;" : "=l"(d) : "l"(a), "l"(b));
    return d;
}
__device__ __forceinline__ u64 add2(u64 a, u64 b) {
    u64 d;
    asm("add.rn.f32x2 %0, %1, %2;" : "=l"(d) : "l"(a), "l"(b));
    return d;
}
__device__ __forceinline__ u64 relu2(u64 v) {
    float lo, hi; unpack2(v, lo, hi);
    lo = fmaxf(lo, 0.0f); hi = fmaxf(hi, 0.0f);
    return pack2(lo, hi);
}

// ---- problem constants ----
constexpr int W_DIM = 4096;
constexpr int C_DIM = 64;
constexpr int L_SEG = 512;              // outputs per warp
constexpr int SEGS  = W_DIM / L_SEG;    // 8
constexpr int BH    = 16 * 21;          // 336 rows
constexpr int WU_IT = 2;                // warmup iterations (64 steps)
constexpr int N_IT  = 18;               // total iterations (576 steps)
constexpr int DEPTH = 3;                // cp.async pipeline depth (blocks)
constexpr int BLK_BYTES = 32 * 256;     // one block: 32 positions x 256 B = 8 KB
constexpr int WARP_SMEM = DEPTH * BLK_BYTES;          // 24 KB per warp
constexpr int SMEM_TOTAL = 4 * WARP_SMEM;             // 96 KB per 128-thr block

// Cross-correlation, zero pad. pad_lo: d=1 -> 3, d=2 -> 7, d=4 -> 14.
// y1[w] = relu(sum_k x [w- 3+  k] * w1[k])
// y2[w] = relu(sum_k y1[w- 7+ 2k] * w2[k])   (y1 := 0 outside [0,W))
// y3[w] = relu(sum_k y2[w-14+ 4k] * w3[k])   (y2 := 0 outside [0,W))
//
// Pipelined schedule (t0 = s0-36):  step i (iter k = i/32, u = i%32):
//   LDS  x pos t0+i+8 from smem blk k (offset u)  -> xr[(u+8)&15]
//   STAGE1 y1 @ t0+i-4  -> y1r[u&15]
//   STAGE2 y2 @ t0+i-12 -> y2r[u&31]
//   STAGE3 y3 @ t0+i-28 -> STG (main iters only; p3 = s0 + 32(k-2) + u)
// smem block b holds positions t0+8+32b .. t0+39+32b (8 KB, contiguous gmem).
// cp.async masks OOB positions with src_size=0 (zero fill) -> no load branches.

__device__ __forceinline__ void prefetch_blk(const char* gsrc, int p0,
                                             unsigned sdst, int lane)
{
    #pragma unroll
    for (int j = 0; j < 16; ++j) {
        const int idx = j * 32 + lane;           // 16B chunk index in the 8KB blk
        const int p   = p0 + (idx >> 4);         // position this chunk belongs to
        const unsigned ok = (p >= 0 && p < W_DIM) ? 16u : 0u;
        asm volatile("cp.async.cg.shared.global [%0], [%1], 16, %2;"
                     :: "r"(sdst + idx * 16), "l"(gsrc + idx * 16), "r"(ok)
                     : "memory");
    }
    asm volatile("cp.async.commit_group;" ::: "memory");
}

#define LDS_STEP(u)                                                            \
    {                                                                          \
        u64 xv;                                                                \
        asm volatile("ld.shared.b64 %0, [%1];" : "=l"(xv)                      \
                     : "r"(cons + (u) * 256));                                 \
        xr[((u) + 8) & 15] = xv;                                               \
    }

#define STAGE1(u)                                                              \
    {                                                                          \
        u64 a0 = mul2(xr[((u) - 7) & 15], w1r[0]);                             \
        u64 a1 = mul2(xr[((u) - 6) & 15], w1r[1]);                             \
        a0 = fma2(xr[((u) - 5) & 15], w1r[2], a0);                             \
        a1 = fma2(xr[((u) - 4) & 15], w1r[3], a1);                             \
        a0 = fma2(xr[((u) - 3) & 15], w1r[4], a0);                             \
        a1 = fma2(xr[((u) - 2) & 15], w1r[5], a1);                             \
        a0 = fma2(xr[((u) - 1) & 15], w1r[6], a0);                             \
        a1 = fma2(xr[((u) - 0) & 15], w1r[7], a1);                             \
        u64 y1v = relu2(add2(a0, a1));                                         \
        if (BOUNDARY) {                                                        \
            const int p1 = pbase + (u) - 4;                                    \
            if (p1 < 0 || p1 >= W_DIM) y1v = 0ull;                             \
        }                                                                      \
        y1r[(u) & 15] = y1v;                                                   \
    }

#define STAGE2(u)                                                              \
    {                                                                          \
        u64 b0 = mul2(y1r[((u) - 15) & 15], w2r[0]);                           \
        u64 b1 = mul2(y1r[((u) - 13) & 15], w2r[1]);                           \
        b0 = fma2(y1r[((u) - 11) & 15], w2r[2], b0);                           \
        b1 = fma2(y1r[((u) -  9) & 15], w2r[3], b1);                           \
        b0 = fma2(y1r[((u) -  7) & 15], w2r[4], b0);                           \
        b1 = fma2(y1r[((u) -  5) & 15], w2r[5], b1);                           \
        b0 = fma2(y1r[((u) -  3) & 15], w2r[6], b0);                           \
        b1 = fma2(y1r[((u) -  1) & 15], w2r[7], b1);                           \
        u64 y2v = relu2(add2(b0, b1));                                         \
        if (BOUNDARY) {                                                        \
            const int p2 = pbase + (u) - 12;                                   \
            if (p2 < 0 || p2 >= W_DIM) y2v = 0ull;                             \
        }                                                                      \
        y2r[(u) & 31] = y2v;                                                   \
    }

#define STAGE3_STORE(u)                                                        \
    {                                                                          \
        u64 c0 = mul2(y2r[((u) - 30) & 31], w3r[0]);                           \
        u64 c1 = mul2(y2r[((u) - 26) & 31], w3r[1]);                           \
        c0 = fma2(y2r[((u) - 22) & 31], w3r[2], c0);                           \
        c1 = fma2(y2r[((u) - 18) & 31], w3r[3], c1);                           \
        c0 = fma2(y2r[((u) - 14) & 31], w3r[4], c0);                           \
        c1 = fma2(y2r[((u) - 10) & 31], w3r[5], c1);                           \
        c0 = fma2(y2r[((u) -  6) & 31], w3r[6], c0);                           \
        c1 = fma2(y2r[((u) -  2) & 31], w3r[7], c1);                           \
        const u64 y3v = relu2(add2(c0, c1));                                   \
        __stcs((u64*)(sp + (u) * C_DIM), y3v);                                 \
    }

template<bool BOUNDARY>
__device__ __forceinline__ void run_seg(
    const float* __restrict__ x,
    const u64* w1r, const u64* w2r, const u64* w3r,
    float* __restrict__ out,
    int bh, int seg, int lane, unsigned wsm)
{
    const int s0 = seg * L_SEG;
    const int t0 = s0 - 36;

    // prefetch stream: block b = positions t0+8+32b .. t0+39+32b (contiguous 8KB)
    const char* gpf = (const char*)x
                    + ((long long)bh * W_DIM + (t0 + 8)) * (C_DIM * 4);
    int ppf = t0 + 8;

    // pre-issue DEPTH blocks
    #pragma unroll
    for (int b = 0; b < DEPTH; ++b) {
        prefetch_blk(gpf, ppf, wsm + b * BLK_BYTES, lane);
        gpf += BLK_BYTES;
        ppf += 32;
    }

    float* sp = out + ((long long)bh * W_DIM + s0) * C_DIM + 2 * lane;
    int pbase = t0;                              // position of step i at u=0

    u64 xr[16], y1r[16], y2r[32];
    #pragma unroll
    for (int j = 0; j < 16; ++j) xr[j]  = 0ull;
    #pragma unroll
    for (int j = 0; j < 16; ++j) y1r[j] = 0ull;
    #pragma unroll
    for (int j = 0; j < 32; ++j) y2r[j] = 0ull;

    unsigned cons = wsm + 2 * lane * 4;          // consume slot 0, lane offset
    const unsigned cons_hi = wsm + DEPTH * BLK_BYTES;

    for (int k = 0; k < N_IT; ++k) {
        if (k == N_IT - 1) asm volatile("cp.async.wait_group 0;" ::: "memory");
        else               asm volatile("cp.async.wait_group 1;" ::: "memory");
        __syncwarp();

        if (k < WU_IT) {
            #pragma unroll
            for (int u = 0; u < 32; ++u) {
                LDS_STEP(u) STAGE1(u) STAGE2(u)
            }
        } else {
            #pragma unroll
            for (int u = 0; u < 32; ++u) {
                LDS_STEP(u) STAGE1(u) STAGE2(u) STAGE3_STORE(u)
            }
            sp += 32 * C_DIM;
        }

        // refill this (just-consumed) slot with block k+DEPTH
        if (k + DEPTH < N_IT) {
            prefetch_blk(gpf, ppf, cons - 2 * lane * 4, lane);
            gpf += BLK_BYTES;
            ppf += 32;
        }

        cons += BLK_BYTES;
        if (cons >= cons_hi) cons -= DEPTH * BLK_BYTES;
        pbase += 32;
    }
}

__global__ void __launch_bounds__(128)
conv_stack_kernel(const float* __restrict__ x,
                  const float* __restrict__ w1,
                  const float* __restrict__ w2,
                  const float* __restrict__ w3,
                  float* __restrict__ out)
{
    extern __shared__ char smem[];

    const int warp = blockIdx.x * 4 + (threadIdx.x >> 5);
    const int lane = threadIdx.x & 31;

    const unsigned wsm = (unsigned)__cvta_generic_to_shared(
        smem + (threadIdx.x >> 5) * WARP_SMEM);

    const int bh  = warp >> 3;        // warp / SEGS
    const int seg = warp & 7;         // warp % SEGS

    u64 w1r[8], w2r[8], w3r[8];
    #pragma unroll
    for (int k = 0; k < 8; ++k) {
        w1r[k] = *(const u64*)(w1 + k * C_DIM + 2 * lane);
        w2r[k] = *(const u64*)(w2 + k * C_DIM + 2 * lane);
        w3r[k] = *(const u64*)(w3 + k * C_DIM + 2 * lane);
    }

    if (seg == 0 || seg == SEGS - 1) {
        run_seg<true >(x, w1r, w2r, w3r, out, bh, seg, lane, wsm);
    } else {
        run_seg<false>(x, w1r, w2r, w3r, out, bh, seg, lane, wsm);
    }
}

extern "C" void kernel_launch(void* const* d_in, const int* in_sizes, int n_in,
                              void* d_out, int out_size)
{
    const float* x  = (const float*)d_in[0];
    const float* w1 = (const float*)d_in[1];
    const float* w2 = (const float*)d_in[2];
    const float* w3 = (const float*)d_in[3];
    float* out = (float*)d_out;

    (void)in_sizes; (void)n_in; (void)out_size;

    cudaFuncSetAttribute(conv_stack_kernel,
                         cudaFuncAttributeMaxDynamicSharedMemorySize, SMEM_TOTAL);

    // 336 rows * 8 segs = 2688 warps -> 672 blocks of 128 threads
    conv_stack_kernel<<<(BH * SEGS) / 4, 128, SMEM_TOTAL>>>(x, w1, w2, w3, out);
}